// round 6
// baseline (speedup 1.0000x reference)
#include <cuda_runtime.h>
#include <math.h>

#define HH   256
#define LL   5
#define TT   1000
#define BB   128

typedef unsigned long long ull;

// Cross-layer mailboxes: one 8-byte {tag=t+1, value} slot per (layer, batch, t).
// Written exactly once per launch; tags zeroed by reset kernel each launch.
__device__ ull   g_mbox[LL - 1][BB][TT];   // 4.096 MB
__device__ float g_hseq[BB][TT];           // layer-4 outputs, 512 KB

__device__ __forceinline__ float tanhapx(float x) {
    float r;
    asm("tanh.approx.f32 %0, %1;" : "=f"(r) : "f"(x));
    return r;
}

__device__ __forceinline__ int redux_s32(int v) {
    int r;
    asm volatile("redux.sync.add.s32 %0, %1, 0xffffffff;" : "=r"(r) : "r"(v));
    return r;
}

// ---------------------------------------------------------------- reset
__global__ void reset_mbox_kernel() {
    ull* p = &g_mbox[0][0][0];
    const int n = (LL - 1) * BB * TT;
    for (int i = blockIdx.x * blockDim.x + threadIdx.x; i < n;
         i += gridDim.x * blockDim.x)
        p[i] = 0ull;
}

// ---------------------------------------------------------------- LSTM pipeline
// grid = LL*BB blocks of 128 threads; block (l, b) runs layer l of batch b.
// Each thread owns 2 hidden channels (h = j, j+128). No block barrier in the
// step loop: cross-warp combine goes through tagged smem slots.
//
// Fixed-point trick: per-lane partial acc is converted to s32 via the
// float magic-number (round(acc * 2^20)); the 4-warp sum s is consumed as
// hp_raw = int_as_float(s + 0x4B400000) = 12582912.0 + s  (exact), with
// wH pre-scaled by 2^-20 and bias pre-shifted by -12582912*wH' so that
// gate = fma(hp_raw, wH', pre) needs no explicit I2F.
__global__ void __launch_bounds__(128)
lstm_layer_kernel(const float* __restrict__ x,
                  const float* __restrict__ Wih,
                  const float* __restrict__ Whh,
                  const float* __restrict__ bih,
                  const float* __restrict__ bhh,
                  const float* __restrict__ Whr)
{
    __shared__ __align__(16) float xbuf[TT];
    __shared__ __align__(16) ull   part[2][4];   // [t&1][warp]

    const int tid  = threadIdx.x;
    const int l    = blockIdx.x >> 7;      // layer
    const int b    = blockIdx.x & 127;     // batch element
    const int w    = tid >> 5;             // warp in block (0..3)
    const int lane = tid & 31;

    const float MAGIC  = 12582912.0f;          // 1.5 * 2^23
    const float SCALE  = 1048576.0f;           // 2^20
    const float INVSCL = 9.5367431640625e-7f;  // 2^-20

    // ---- per-thread weights: 2 channels x 4 gates ----
    // gate order i,f,g,o; sigmoid(x)=0.5*tanh(0.5x)+0.5 with 0.5 folded in.
    // wH additionally scaled by 2^-20 and bias shifted by -MAGIC*wH' so the
    // raw (magic-biased) hp feeds the gate FMA directly.
    float wI[2][4], wH[2][4], bS[2][4], wR[2];
#pragma unroll
    for (int ch = 0; ch < 2; ++ch) {
        int h = tid + ch * 128;
#pragma unroll
        for (int g = 0; g < 4; ++g) {
            int idx = l * 1024 + g * 256 + h;
            float s = (g == 2) ? 1.0f : 0.5f;
            float wh = Whh[idx] * s * INVSCL;
            wI[ch][g] = Wih[idx] * s;
            wH[ch][g] = wh;
            bS[ch][g] = (bih[idx] + bhh[idx]) * s - MAGIC * wh;
        }
        wR[ch] = Whr[l * 256 + h];
    }

    if (l == 0) {
        for (int k = tid; k < TT; k += 128)
            xbuf[k] = x[b * TT + k];
    }
    __syncthreads();

    const ull* mb_in  = (l > 0) ? g_mbox[l - 1][b] : (const ull*)0;
    ull*       mb_out = (l < LL - 1) ? g_mbox[l][b] : (ull*)0;

    float c0 = 0.0f, c1 = 0.0f;
    // hp_raw for t=0: s=0 -> MAGIC
    float hp_raw = MAGIC;

    // input prefetch state
    float xin = 0.0f;
    ull   pre = 0ull;
    if (l == 0) xin = xbuf[0];
    else        pre = *(volatile const ull*)mb_in;

    for (int t = 0; t < TT; ++t) {
        // ---- obtain input (register-resident in steady state) ----
        float in;
        if (l == 0) {
            in = xin;
        } else {
            ull v = pre;
            const unsigned want = (unsigned)(t + 1);
            while ((unsigned)(v >> 32) != want)
                v = *(volatile const ull*)(mb_in + t);
            in = __uint_as_float((unsigned)v);
        }

        // ---- two channels of the LSTM cell ----
        float acc;
        {   // channel 0
            float gi = fmaf(hp_raw, wH[0][0], fmaf(in, wI[0][0], bS[0][0]));
            float gf = fmaf(hp_raw, wH[0][1], fmaf(in, wI[0][1], bS[0][1]));
            float gg = fmaf(hp_raw, wH[0][2], fmaf(in, wI[0][2], bS[0][2]));
            float go = fmaf(hp_raw, wH[0][3], fmaf(in, wI[0][3], bS[0][3]));
            float i_ = fmaf(tanhapx(gi), 0.5f, 0.5f);
            float f_ = fmaf(tanhapx(gf), 0.5f, 0.5f);
            float g_ = tanhapx(gg);
            float o_ = fmaf(tanhapx(go), 0.5f, 0.5f);
            c0 = fmaf(f_, c0, i_ * g_);
            acc = (o_ * tanhapx(c0)) * wR[0];
        }
        {   // channel 1
            float gi = fmaf(hp_raw, wH[1][0], fmaf(in, wI[1][0], bS[1][0]));
            float gf = fmaf(hp_raw, wH[1][1], fmaf(in, wI[1][1], bS[1][1]));
            float gg = fmaf(hp_raw, wH[1][2], fmaf(in, wI[1][2], bS[1][2]));
            float go = fmaf(hp_raw, wH[1][3], fmaf(in, wI[1][3], bS[1][3]));
            float i_ = fmaf(tanhapx(gi), 0.5f, 0.5f);
            float f_ = fmaf(tanhapx(gf), 0.5f, 0.5f);
            float g_ = tanhapx(gg);
            float o_ = fmaf(tanhapx(go), 0.5f, 0.5f);
            c1 = fmaf(f_, c1, i_ * g_);
            acc = fmaf(o_ * tanhapx(c1), wR[1], acc);
        }

        // ---- fixed-point conversion (magic number) + warp redux ----
        int q = __float_as_int(fmaf(acc, SCALE, MAGIC)) - 0x4B400000;
        int r = redux_s32(q);                    // full warp sum, all lanes

        // ---- cross-warp combine via tagged smem slots (no barrier) ----
        if (lane == 0)
            *(volatile ull*)&part[t & 1][w] =
                ((ull)(unsigned)(t + 1) << 32) | (ull)(unsigned)r;

        // prefetch next input while waiting for the other warps
        if (l == 0) {
            if (t + 1 < TT) xin = xbuf[t + 1];
        } else {
            if (t + 1 < TT) pre = *(volatile const ull*)(mb_in + t + 1);
        }

        int s = r;
        const unsigned want = (unsigned)(t + 1);
#pragma unroll
        for (int k = 1; k < 4; ++k) {
            volatile ull* slot = (volatile ull*)&part[t & 1][(w + k) & 3];
            ull v = *slot;
            while ((unsigned)(v >> 32) != want) v = *slot;
            s += (int)(unsigned)v;
        }
        hp_raw = __int_as_float(s + 0x4B400000);   // = MAGIC + (float)s

        // ---- publish true h (only needed cross-layer / for the head) ----
        if (tid == 0) {
            float hval = (hp_raw - MAGIC) * INVSCL;
            if (mb_out) {
                ull v = ((ull)(unsigned)(t + 1) << 32) |
                        (ull)__float_as_uint(hval);
                *(volatile ull*)(mb_out + t) = v;
            } else {
                g_hseq[b][t] = hval;
            }
        }
    }
}

// ---------------------------------------------------------------- MLP head
__global__ void __launch_bounds__(128)
mlp_kernel(const float* __restrict__ W1, const float* __restrict__ b1,
           const float* __restrict__ W2, const float* __restrict__ b2,
           const float* __restrict__ W3, const float* __restrict__ b3,
           const float* __restrict__ W4, const float* __restrict__ b4,
           float* __restrict__ out)
{
    __shared__ __align__(16) float hbuf[TT];
    __shared__ float a1[100], a2[100], a3[100];

    const int tid = threadIdx.x;
    const int b   = blockIdx.x;

    for (int k = tid; k < TT; k += 128)
        hbuf[k] = g_hseq[b][k];
    __syncthreads();

    if (tid < 100) {
        const float* wrow = W1 + tid * 1000;
        float acc0 = 0.f, acc1 = 0.f, acc2 = 0.f, acc3 = 0.f;
#pragma unroll 2
        for (int k = 0; k < 1000; k += 4) {
            float4 wv = *(const float4*)(wrow + k);
            float4 hv = *(const float4*)(hbuf + k);
            acc0 = fmaf(wv.x, hv.x, acc0);
            acc1 = fmaf(wv.y, hv.y, acc1);
            acc2 = fmaf(wv.z, hv.z, acc2);
            acc3 = fmaf(wv.w, hv.w, acc3);
        }
        float acc = ((acc0 + acc1) + (acc2 + acc3)) + b1[tid];
        a1[tid] = 1.0f / (1.0f + expf(-acc));
    }
    __syncthreads();
    if (tid < 100) {
        const float* wrow = W2 + tid * 100;
        float acc = b2[tid];
#pragma unroll 4
        for (int k = 0; k < 100; ++k)
            acc = fmaf(wrow[k], a1[k], acc);
        a2[tid] = 1.0f / (1.0f + expf(-acc));
    }
    __syncthreads();
    if (tid < 100) {
        const float* wrow = W3 + tid * 100;
        float acc = b3[tid];
#pragma unroll 4
        for (int k = 0; k < 100; ++k)
            acc = fmaf(wrow[k], a2[k], acc);
        a3[tid] = fmaxf(acc, 0.0f);
    }
    __syncthreads();
    if (tid == 0) {
        float acc = b4[0];
#pragma unroll 4
        for (int k = 0; k < 100; ++k)
            acc = fmaf(W4[k], a3[k], acc);
        out[b] = acc;
    }
}

extern "C" void kernel_launch(void* const* d_in, const int* in_sizes, int n_in,
                              void* d_out, int out_size)
{
    const float* x   = (const float*)d_in[0];
    const float* Wih = (const float*)d_in[1];
    const float* Whh = (const float*)d_in[2];
    const float* bih = (const float*)d_in[3];
    const float* bhh = (const float*)d_in[4];
    const float* Whr = (const float*)d_in[5];
    const float* W1  = (const float*)d_in[6];
    const float* b1  = (const float*)d_in[7];
    const float* W2  = (const float*)d_in[8];
    const float* b2  = (const float*)d_in[9];
    const float* W3  = (const float*)d_in[10];
    const float* b3  = (const float*)d_in[11];
    const float* W4  = (const float*)d_in[12];
    const float* b4  = (const float*)d_in[13];
    float* out = (float*)d_out;

    reset_mbox_kernel<<<480, 256>>>();
    lstm_layer_kernel<<<LL * BB, 128>>>(x, Wih, Whh, bih, bhh, Whr);
    mlp_kernel<<<BB, 128>>>(W1, b1, W2, b2, W3, b3, W4, b4, out);
}

// round 7
// speedup vs baseline: 1.0865x; 1.0865x over previous
#include <cuda_runtime.h>
#include <math.h>

#define HH   256
#define LL   5
#define TT   1000
#define BB   128

typedef unsigned long long ull;

// Cross-layer mailboxes: one 8-byte {tag=t+1, value} slot per (layer, batch, t).
// Written exactly once per launch; tags zeroed by reset kernel each launch.
__device__ ull   g_mbox[LL - 1][BB][TT];   // 4.096 MB
__device__ float g_hseq[BB][TT];           // layer-4 outputs, 512 KB

__device__ __forceinline__ float tanhapx(float x) {
    float r;
    asm("tanh.approx.f32 %0, %1;" : "=f"(r) : "f"(x));
    return r;
}

__device__ __forceinline__ int redux_s32(int v) {
    int r;
    asm volatile("redux.sync.add.s32 %0, %1, 0xffffffff;" : "=r"(r) : "r"(v));
    return r;
}

// ---------------------------------------------------------------- reset
__global__ void reset_mbox_kernel() {
    ull* p = &g_mbox[0][0][0];
    const int n = (LL - 1) * BB * TT;
    for (int i = blockIdx.x * blockDim.x + threadIdx.x; i < n;
         i += gridDim.x * blockDim.x)
        p[i] = 0ull;
}

// ---------------------------------------------------------------- LSTM pipeline
// grid = LL*BB blocks of 128 threads; block (l, b) runs layer l of batch b.
// Each thread owns 2 hidden channels (h = tid, tid+128).
//
// Chain-shortening tricks:
//  * magic-number fixed point: q = float_as_int(fma(acc, 2^20, MAGIC)) - BITS;
//    4-warp sum s is consumed as hp_raw = int_as_float(s + BITS) = MAGIC + s,
//    with wH pre-scaled by 2^-20 and bias shifted by -MAGIC*wH' so gates use
//    hp_raw directly (no I2F/F2I anywhere on the chain).
//  * pre-gates: pg = fma(in, wI, bS) depends only on the prefetched input, so
//    step t+1's 8 input-side FMAs run BEFORE the barrier, inside the wait.
//  * partial combine is one LDS.128 (int4) + 3 adds after __syncthreads.
__global__ void __launch_bounds__(128)
lstm_layer_kernel(const float* __restrict__ x,
                  const float* __restrict__ Wih,
                  const float* __restrict__ Whh,
                  const float* __restrict__ bih,
                  const float* __restrict__ bhh,
                  const float* __restrict__ Whr)
{
    __shared__ __align__(16) float xbuf[TT];
    __shared__ __align__(16) int   part[2][4];   // [t&1][warp]

    const int tid  = threadIdx.x;
    const int l    = blockIdx.x >> 7;      // layer
    const int b    = blockIdx.x & 127;     // batch element
    const int w    = tid >> 5;             // warp in block (0..3)
    const int lane = tid & 31;

    const float MAGIC  = 12582912.0f;          // 1.5 * 2^23
    const int   MBITS  = 0x4B400000;           // bit pattern of MAGIC
    const float SCALE  = 1048576.0f;           // 2^20
    const float INVSCL = 9.5367431640625e-7f;  // 2^-20

    // ---- per-thread weights: 2 channels x 4 gates ----
    // gate order i,f,g,o; sigmoid(x)=0.5*tanh(0.5x)+0.5 with 0.5 folded in.
    float wI[2][4], wH[2][4], bS[2][4], wR[2];
#pragma unroll
    for (int ch = 0; ch < 2; ++ch) {
        int h = tid + ch * 128;
#pragma unroll
        for (int g = 0; g < 4; ++g) {
            int idx = l * 1024 + g * 256 + h;
            float s = (g == 2) ? 1.0f : 0.5f;
            float wh = Whh[idx] * s * INVSCL;
            wI[ch][g] = Wih[idx] * s;
            wH[ch][g] = wh;
            bS[ch][g] = (bih[idx] + bhh[idx]) * s - MAGIC * wh;
        }
        wR[ch] = Whr[l * 256 + h];
    }

    if (l == 0) {
        for (int k = tid; k < TT; k += 128)
            xbuf[k] = x[b * TT + k];
    }
    __syncthreads();

    const ull* mb_in  = (l > 0) ? g_mbox[l - 1][b] : (const ull*)0;
    ull*       mb_out = (l < LL - 1) ? g_mbox[l][b] : (ull*)0;

    float c0 = 0.0f, c1 = 0.0f;
    float hp_raw = MAGIC;            // s=0 at t=0

    // ---- obtain in_0 and compute its pre-gates ----
    float pg[2][4];
    {
        float in0;
        if (l == 0) {
            in0 = xbuf[0];
        } else {
            ull v = *(volatile const ull*)mb_in;
            while ((unsigned)(v >> 32) != 1u)
                v = *(volatile const ull*)mb_in;
            in0 = __uint_as_float((unsigned)v);
        }
#pragma unroll
        for (int ch = 0; ch < 2; ++ch)
#pragma unroll
            for (int g = 0; g < 4; ++g)
                pg[ch][g] = fmaf(in0, wI[ch][g], bS[ch][g]);
    }

    for (int t = 0; t < TT; ++t) {
        // ---- post-barrier chain: gates depend only on hp_raw + pre-gates ----
        float acc;
        {   // channel 0
            float gi = fmaf(hp_raw, wH[0][0], pg[0][0]);
            float gf = fmaf(hp_raw, wH[0][1], pg[0][1]);
            float gg = fmaf(hp_raw, wH[0][2], pg[0][2]);
            float go = fmaf(hp_raw, wH[0][3], pg[0][3]);
            float i_ = fmaf(tanhapx(gi), 0.5f, 0.5f);
            float f_ = fmaf(tanhapx(gf), 0.5f, 0.5f);
            float g_ = tanhapx(gg);
            float o_ = fmaf(tanhapx(go), 0.5f, 0.5f);
            c0 = fmaf(f_, c0, i_ * g_);
            acc = (o_ * tanhapx(c0)) * wR[0];
        }
        {   // channel 1
            float gi = fmaf(hp_raw, wH[1][0], pg[1][0]);
            float gf = fmaf(hp_raw, wH[1][1], pg[1][1]);
            float gg = fmaf(hp_raw, wH[1][2], pg[1][2]);
            float go = fmaf(hp_raw, wH[1][3], pg[1][3]);
            float i_ = fmaf(tanhapx(gi), 0.5f, 0.5f);
            float f_ = fmaf(tanhapx(gf), 0.5f, 0.5f);
            float g_ = tanhapx(gg);
            float o_ = fmaf(tanhapx(go), 0.5f, 0.5f);
            c1 = fmaf(f_, c1, i_ * g_);
            acc = fmaf(o_ * tanhapx(c1), wR[1], acc);
        }

        // ---- fixed-point (magic) + warp redux; lane0 posts warp partial ----
        int q = __float_as_int(fmaf(acc, SCALE, MAGIC)) - MBITS;
        int r = redux_s32(q);
        if (lane == 0) part[t & 1][w] = r;

        // ---- fill the barrier window: fetch in_{t+1}, compute its pre-gates ----
        if (t + 1 < TT) {
            float in;
            if (l == 0) {
                in = xbuf[t + 1];
            } else {
                ull v = *(volatile const ull*)(mb_in + t + 1);
                const unsigned want = (unsigned)(t + 2);
                while ((unsigned)(v >> 32) != want)
                    v = *(volatile const ull*)(mb_in + t + 1);
                in = __uint_as_float((unsigned)v);
            }
#pragma unroll
            for (int ch = 0; ch < 2; ++ch)
#pragma unroll
                for (int g = 0; g < 4; ++g)
                    pg[ch][g] = fmaf(in, wI[ch][g], bS[ch][g]);
        }

        __syncthreads();

        // ---- combine 4 warp partials: one LDS.128 + 3 adds ----
        int4 pp = *(const int4*)&part[t & 1][0];
        int s = (pp.x + pp.y) + (pp.z + pp.w);
        hp_raw = __int_as_float(s + MBITS);        // = MAGIC + (float)s

        // ---- publish true h (cross-layer / head) ----
        if (tid == 0) {
            float hval = (hp_raw - MAGIC) * INVSCL;
            if (mb_out) {
                ull v = ((ull)(unsigned)(t + 1) << 32) |
                        (ull)__float_as_uint(hval);
                *(volatile ull*)(mb_out + t) = v;
            } else {
                g_hseq[b][t] = hval;
            }
        }
    }
}

// ---------------------------------------------------------------- MLP head
__global__ void __launch_bounds__(128)
mlp_kernel(const float* __restrict__ W1, const float* __restrict__ b1,
           const float* __restrict__ W2, const float* __restrict__ b2,
           const float* __restrict__ W3, const float* __restrict__ b3,
           const float* __restrict__ W4, const float* __restrict__ b4,
           float* __restrict__ out)
{
    __shared__ __align__(16) float hbuf[TT];
    __shared__ float a1[100], a2[100], a3[100];

    const int tid = threadIdx.x;
    const int b   = blockIdx.x;

    for (int k = tid; k < TT; k += 128)
        hbuf[k] = g_hseq[b][k];
    __syncthreads();

    if (tid < 100) {
        const float* wrow = W1 + tid * 1000;
        float acc0 = 0.f, acc1 = 0.f, acc2 = 0.f, acc3 = 0.f;
#pragma unroll 2
        for (int k = 0; k < 1000; k += 4) {
            float4 wv = *(const float4*)(wrow + k);
            float4 hv = *(const float4*)(hbuf + k);
            acc0 = fmaf(wv.x, hv.x, acc0);
            acc1 = fmaf(wv.y, hv.y, acc1);
            acc2 = fmaf(wv.z, hv.z, acc2);
            acc3 = fmaf(wv.w, hv.w, acc3);
        }
        float acc = ((acc0 + acc1) + (acc2 + acc3)) + b1[tid];
        a1[tid] = 1.0f / (1.0f + expf(-acc));
    }
    __syncthreads();
    if (tid < 100) {
        const float* wrow = W2 + tid * 100;
        float acc = b2[tid];
#pragma unroll 4
        for (int k = 0; k < 100; ++k)
            acc = fmaf(wrow[k], a1[k], acc);
        a2[tid] = 1.0f / (1.0f + expf(-acc));
    }
    __syncthreads();
    if (tid < 100) {
        const float* wrow = W3 + tid * 100;
        float acc = b3[tid];
#pragma unroll 4
        for (int k = 0; k < 100; ++k)
            acc = fmaf(wrow[k], a2[k], acc);
        a3[tid] = fmaxf(acc, 0.0f);
    }
    __syncthreads();
    if (tid == 0) {
        float acc = b4[0];
#pragma unroll 4
        for (int k = 0; k < 100; ++k)
            acc = fmaf(W4[k], a3[k], acc);
        out[b] = acc;
    }
}

extern "C" void kernel_launch(void* const* d_in, const int* in_sizes, int n_in,
                              void* d_out, int out_size)
{
    const float* x   = (const float*)d_in[0];
    const float* Wih = (const float*)d_in[1];
    const float* Whh = (const float*)d_in[2];
    const float* bih = (const float*)d_in[3];
    const float* bhh = (const float*)d_in[4];
    const float* Whr = (const float*)d_in[5];
    const float* W1  = (const float*)d_in[6];
    const float* b1  = (const float*)d_in[7];
    const float* W2  = (const float*)d_in[8];
    const float* b2  = (const float*)d_in[9];
    const float* W3  = (const float*)d_in[10];
    const float* b3  = (const float*)d_in[11];
    const float* W4  = (const float*)d_in[12];
    const float* b4  = (const float*)d_in[13];
    float* out = (float*)d_out;

    reset_mbox_kernel<<<480, 256>>>();
    lstm_layer_kernel<<<LL * BB, 128>>>(x, Wih, Whh, bih, bhh, Whr);
    mlp_kernel<<<BB, 128>>>(W1, b1, W2, b2, W3, b3, W4, b4, out);
}